// round 14
// baseline (speedup 1.0000x reference)
#include <cuda_runtime.h>
#include <cuda_bf16.h>
#include <math.h>
#include <stdint.h>

#define BATCH 256
#define NODE  512
#define WIN   64
#define EMB   64
#define TOPK  16
#define INTER 512
#define NT    (BATCH*NODE)     /* 131072 */
#define NEG   0.2f
#define EPS   1e-5f

// ---------------- scratch (static device globals) ----------------
__device__ float g_xl[NT*EMB];
__device__ float g_agg[NT*EMB];
__device__ __align__(16) uint32_t g_zrh[NT*EMB/2];   // bf16x2, fragperm word order
__device__ __align__(16) uint32_t g_zrl[NT*EMB/2];
__device__ __align__(16) uint32_t g_W1h[INTER*EMB/2]; // fragperm word order
__device__ __align__(16) uint32_t g_W1l[INTER*EMB/2];
__device__ float g_si[NT];
__device__ float g_sj[NT];
__device__ int   g_topk[NODE*TOPK];
__device__ float g_ei[NODE], g_ej[NODE], g_inv[NODE];
// [0:64]=bn1 sum  [64:128]=bn1 sq  [128:192]=bn2 sum [192:256]=bn2 sq
// [256:320]=zr colsum  [320:4416]=M2 (64x64 second moment of zr)
__device__ float g_stats[4416];
__device__ float4 g_abc[INTER];   // {bn3_scale, bn3_shift, W2, 0}

// ---------------- HMMA helper ----------------
__device__ __forceinline__ void mma16816(float* d, const uint32_t* a, uint32_t b0, uint32_t b1) {
    asm volatile("mma.sync.aligned.m16n8k16.row.col.f32.bf16.bf16.f32 "
        "{%0,%1,%2,%3}, {%4,%5,%6,%7}, {%8,%9}, {%0,%1,%2,%3};"
        : "+f"(d[0]), "+f"(d[1]), "+f"(d[2]), "+f"(d[3])
        : "r"(a[0]), "r"(a[1]), "r"(a[2]), "r"(a[3]), "r"(b0), "r"(b1));
}
// fragment-order permutation of a 32-word (64 bf16) k-row
__device__ __forceinline__ int fragperm(int k2) {
    return (k2 & 3)*8 + (k2 >> 3)*2 + ((k2 >> 2) & 1);
}
__device__ __forceinline__ uint32_t packsplit(float x, float y, uint32_t* lo) {
    __nv_bfloat16 h0 = __float2bfloat16(x);
    __nv_bfloat16 h1 = __float2bfloat16(y);
    __nv_bfloat162 l2 = __halves2bfloat162(__float2bfloat16(x - __bfloat162float(h0)),
                                           __float2bfloat16(y - __bfloat162float(h1)));
    *lo = *(uint32_t*)&l2;
    __nv_bfloat162 h2 = __halves2bfloat162(h0, h1);
    return *(uint32_t*)&h2;
}

// ---------------- prep: zero stats + out; embed dots/norms; W1 hi/lo ----------------
__global__ void k_prep(const float* __restrict__ W_emb,
                       const float* __restrict__ aei,
                       const float* __restrict__ aej,
                       const float* __restrict__ W1,
                       float* __restrict__ out) {
    int t = threadIdx.x, b = blockIdx.x;
    if (b == 0) {
        for (int i = t; i < 4416; i += blockDim.x) g_stats[i] = 0.f;
    } else if (b == 1) {
        int v = t;
        const float* w = W_emb + v*EMB;
        float di = 0.f, dj = 0.f, nn = 0.f;
        #pragma unroll
        for (int k = 0; k < EMB; k++) {
            float x = w[k];
            di += x*aei[k]; dj += x*aej[k]; nn += x*x;
        }
        g_ei[v] = di; g_ej[v] = dj; g_inv[v] = rsqrtf(nn);
    } else if (b < 66) {
        float4* o4 = (float4*)out;
        int idx = (b - 2)*512 + t;              // 64 blocks * 512 threads = 32768 float4
        o4[idx] = make_float4(0.f, 0.f, 0.f, 0.f);
    } else {
        int i = (b - 66)*512 + t;               // 32 blocks: W1 split
        if (i < INTER*EMB/2) {
            float2 w = ((const float2*)W1)[i];
            uint32_t lo, hi = packsplit(w.x, w.y, &lo);
            int n = i >> 5, k2 = i & 31;
            int j = n*32 + fragperm(k2);
            g_W1h[j] = hi;
            g_W1l[j] = lo;
        }
    }
}

// ---------------- cosine-similarity top-k: one WARP per node, no barriers ----------------
__global__ void k_topk(const float* __restrict__ W_emb) {
    int t = threadIdx.x, lane = t & 31, w = t >> 5;
    int i = blockIdx.x*8 + w;   // node
    float wi[64];
    const float4* wi4 = (const float4*)&W_emb[i*64];
    #pragma unroll
    for (int k = 0; k < 16; k++) {
        float4 v = wi4[k];
        wi[k*4] = v.x; wi[k*4+1] = v.y; wi[k*4+2] = v.z; wi[k*4+3] = v.w;
    }
    float inv_i = g_inv[i];
    float cosv[16]; int jidx[16];
    #pragma unroll
    for (int q = 0; q < 16; q++) {
        int j = lane + q*32;
        const float4* wj = (const float4*)&W_emb[j*64];
        float d = 0.f;
        #pragma unroll
        for (int kk = 0; kk < 16; kk++) {
            float4 b = wj[kk];
            d += wi[kk*4]*b.x + wi[kk*4+1]*b.y + wi[kk*4+2]*b.z + wi[kk*4+3]*b.w;
        }
        cosv[q] = d * inv_i * g_inv[j];
        jidx[q] = j;
    }
    for (int s = 0; s < TOPK; s++) {
        float bv = -3e38f; int bj = NODE;
        #pragma unroll
        for (int q = 0; q < 16; q++) {
            if (cosv[q] > bv || (cosv[q] == bv && jidx[q] < bj)) { bv = cosv[q]; bj = jidx[q]; }
        }
        #pragma unroll
        for (int o = 16; o > 0; o >>= 1) {
            float v2 = __shfl_xor_sync(0xffffffffu, bv, o);
            int  j2 = __shfl_xor_sync(0xffffffffu, bj, o);
            if (v2 > bv || (v2 == bv && j2 < bj)) { bv = v2; bj = j2; }
        }
        if (lane == (bj & 31)) {
            int qi = bj >> 5;
            #pragma unroll
            for (int q = 0; q < 16; q++) if (q == qi) cosv[q] = -3e38f;
        }
        if (lane == 0) g_topk[i*TOPK + s] = bj;
    }
}

// ---------------- xl = x @ W_lin^T via HMMA split + fused attention scores ----------------
#define XL_BH 0
#define XL_BL 2304
#define XL_AH 4608
#define XL_AL 9216
#define XL_AI 13824
#define XL_AJ 13888
#define SMEM_XL (13952*4)
__global__ void __launch_bounds__(256, 2)
k_xl_mma(const float* __restrict__ x, const float* __restrict__ W_lin,
         const float* __restrict__ att_i, const float* __restrict__ att_j) {
    extern __shared__ uint32_t smx[];
    uint32_t* Bh = smx + XL_BH;
    uint32_t* Bl = smx + XL_BL;
    uint32_t* Ah = smx + XL_AH;
    uint32_t* Al = smx + XL_AL;
    float* ai = (float*)(smx + XL_AI);
    float* aj = (float*)(smx + XL_AJ);
    int t = threadIdx.x, lane = t & 31, wid = t >> 5;
    int g = lane >> 2, tid = lane & 3;
    for (int i = t; i < 64*32; i += 256) {
        int e = i >> 5, k2 = i & 31;
        float2 w = ((const float2*)W_lin)[i];
        uint32_t lo, hi = packsplit(w.x, w.y, &lo);
        int j = fragperm(k2);
        Bh[e*36 + j] = hi; Bl[e*36 + j] = lo;
    }
    if (t < 64) { ai[t] = att_i[t]; aj[t] = att_j[t]; }
    int r0 = wid*16 + g;
    for (int tile = blockIdx.x; tile < NT/128; tile += gridDim.x) {
        int row0 = tile << 7;
        __syncthreads();
        for (int i = t; i < 128*32; i += 256) {
            int r = i >> 5, k2 = i & 31;
            float2 v = ((const float2*)x)[row0*32 + i];
            uint32_t lo, hi = packsplit(v.x, v.y, &lo);
            int j = fragperm(k2);
            Ah[r*36 + j] = hi; Al[r*36 + j] = lo;
        }
        __syncthreads();
        uint4 qh0 = *(const uint4*)&Ah[r0*36 + tid*8];
        uint4 qh1 = *(const uint4*)&Ah[r0*36 + tid*8 + 4];
        uint4 qh2 = *(const uint4*)&Ah[(r0+8)*36 + tid*8];
        uint4 qh3 = *(const uint4*)&Ah[(r0+8)*36 + tid*8 + 4];
        uint4 ql0 = *(const uint4*)&Al[r0*36 + tid*8];
        uint4 ql1 = *(const uint4*)&Al[r0*36 + tid*8 + 4];
        uint4 ql2 = *(const uint4*)&Al[(r0+8)*36 + tid*8];
        uint4 ql3 = *(const uint4*)&Al[(r0+8)*36 + tid*8 + 4];
        uint32_t ah[4][4] = {
            {qh0.x, qh2.x, qh0.y, qh2.y}, {qh0.z, qh2.z, qh0.w, qh2.w},
            {qh1.x, qh3.x, qh1.y, qh3.y}, {qh1.z, qh3.z, qh1.w, qh3.w}};
        uint32_t al[4][4] = {
            {ql0.x, ql2.x, ql0.y, ql2.y}, {ql0.z, ql2.z, ql0.w, ql2.w},
            {ql1.x, ql3.x, ql1.y, ql3.y}, {ql1.z, ql3.z, ql1.w, ql3.w}};
        float pi0=0, pi1=0, pj0=0, pj1=0;
        #pragma unroll
        for (int nt = 0; nt < 8; nt++) {
            int nb = (nt*8 + g)*36 + tid*8;
            uint4 bh0 = *(const uint4*)&Bh[nb], bh1 = *(const uint4*)&Bh[nb+4];
            uint4 bl0 = *(const uint4*)&Bl[nb], bl1 = *(const uint4*)&Bl[nb+4];
            float hh[4]={0,0,0,0}, hl[4]={0,0,0,0}, lh[4]={0,0,0,0};
            mma16816(hh, ah[0], bh0.x, bh0.y); mma16816(hh, ah[1], bh0.z, bh0.w);
            mma16816(hh, ah[2], bh1.x, bh1.y); mma16816(hh, ah[3], bh1.z, bh1.w);
            mma16816(hl, ah[0], bl0.x, bl0.y); mma16816(hl, ah[1], bl0.z, bl0.w);
            mma16816(hl, ah[2], bl1.x, bl1.y); mma16816(hl, ah[3], bl1.z, bl1.w);
            mma16816(lh, al[0], bh0.x, bh0.y); mma16816(lh, al[1], bh0.z, bh0.w);
            mma16816(lh, al[2], bh1.x, bh1.y); mma16816(lh, al[3], bh1.z, bh1.w);
            float v0 = hh[0]+hl[0]+lh[0], v1 = hh[1]+hl[1]+lh[1];
            float v2 = hh[2]+hl[2]+lh[2], v3 = hh[3]+hl[3]+lh[3];
            int col = nt*8 + tid*2;
            *(float2*)&g_xl[(row0+r0)*64 + col]   = make_float2(v0, v1);
            *(float2*)&g_xl[(row0+r0+8)*64 + col] = make_float2(v2, v3);
            float a0 = ai[col], a1 = ai[col+1], j0 = aj[col], j1 = aj[col+1];
            pi0 += v0*a0 + v1*a1;  pj0 += v0*j0 + v1*j1;
            pi1 += v2*a0 + v3*a1;  pj1 += v2*j0 + v3*j1;
        }
        pi0 += __shfl_xor_sync(0xffffffffu, pi0, 1); pi0 += __shfl_xor_sync(0xffffffffu, pi0, 2);
        pj0 += __shfl_xor_sync(0xffffffffu, pj0, 1); pj0 += __shfl_xor_sync(0xffffffffu, pj0, 2);
        pi1 += __shfl_xor_sync(0xffffffffu, pi1, 1); pi1 += __shfl_xor_sync(0xffffffffu, pi1, 2);
        pj1 += __shfl_xor_sync(0xffffffffu, pj1, 1); pj1 += __shfl_xor_sync(0xffffffffu, pj1, 2);
        if (tid == 0) {
            int n0 = row0 + r0, v = n0 & (NODE-1);
            g_si[n0] = pi0 + g_ei[v]; g_sj[n0] = pj0 + g_ej[v];
            n0 += 8; v = n0 & (NODE-1);
            g_si[n0] = pi1 + g_ei[v]; g_sj[n0] = pj1 + g_ej[v];
        }
    }
}

// ---------------- GAT aggregation: 1024 thr, half-warp node split, float4 gather ----------------
// smem floats: sxl[512*64]=32768, stk ints 8192 @32768, ssi @40960, ssj @41472,
//              sms @41984, smq @42048; total 42112 floats = 168448 B (1 CTA/SM, 32 warps)
#define SMEM_AGG (42112*4)
__global__ void __launch_bounds__(1024, 1)
k_agg(const float* __restrict__ b_gnn) {
    extern __shared__ float smA[];
    float* sxl = smA;
    int*   stk = (int*)(smA + 32768);
    float* ssi = smA + 40960;
    float* ssj = smA + 41472;
    float* sms = smA + 41984;
    float* smq = smA + 42048;
    int t = threadIdx.x, wid = t >> 5, lane = t & 31;
    int b = blockIdx.x;
    const float4* src = (const float4*)&g_xl[b*NODE*EMB];
    float4* dst4 = (float4*)sxl;
    for (int i = t; i < 512*16; i += 1024) dst4[i] = src[i];
    for (int i = t; i < NODE*TOPK; i += 1024) stk[i] = g_topk[i];
    if (t < NODE) { ssi[t] = g_si[b*NODE + t]; ssj[t] = g_sj[b*NODE + t]; }
    if (t < 64) { sms[t] = 0.f; smq[t] = 0.f; }
    __syncthreads();
    int k = lane & 15, half = lane >> 4;
    int srcoff = half << 4;
    float4 bg4 = *(const float4*)&b_gnn[k*4];
    const float4* sxl4 = (const float4*)sxl;
    float4 s4 = make_float4(0.f,0.f,0.f,0.f);
    float4 q4 = make_float4(0.f,0.f,0.f,0.f);
    int vbase = wid*16;       // 32 warps * 16 nodes = 512
    #pragma unroll 1
    for (int vp = 0; vp < 8; vp++) {
        // lanes 0-15: softmax + gather for node vA; lanes 16-31: node vB = vA+1
        int v = vbase + vp*2 + half;
        int nbr = stk[v*16 + k];
        float a = ssi[v] + ssj[nbr];
        a = a > 0.f ? a : NEG*a;
        float m = a;
        #pragma unroll
        for (int o = 8; o > 0; o >>= 1) m = fmaxf(m, __shfl_xor_sync(0xffffffffu, m, o, 16));
        float ex = expf(a - m);
        float den = ex;
        #pragma unroll
        for (int o = 8; o > 0; o >>= 1) den += __shfl_xor_sync(0xffffffffu, den, o, 16);
        float w = ex / den;
        // gather: lane handles 4 channels (k*4..k*4+3) of its own node
        float4 acc = make_float4(0.f,0.f,0.f,0.f);
        #pragma unroll
        for (int kk = 0; kk < 16; kk++) {
            float wk = __shfl_sync(0xffffffffu, w,   kk + srcoff);
            int   nb = __shfl_sync(0xffffffffu, nbr, kk + srcoff);
            float4 vv = sxl4[nb*16 + k];
            acc.x = fmaf(wk, vv.x, acc.x);
            acc.y = fmaf(wk, vv.y, acc.y);
            acc.z = fmaf(wk, vv.z, acc.z);
            acc.w = fmaf(wk, vv.w, acc.w);
        }
        *(float4*)&g_agg[(b*NODE + v)*EMB + k*4] = acc;
        float z0 = acc.x + bg4.x, z1 = acc.y + bg4.y;
        float z2 = acc.z + bg4.z, z3 = acc.w + bg4.w;
        s4.x += z0; q4.x += z0*z0; s4.y += z1; q4.y += z1*z1;
        s4.z += z2; q4.z += z2*z2; s4.w += z3; q4.w += z3*z3;
    }
    atomicAdd(&sms[k*4+0], s4.x); atomicAdd(&smq[k*4+0], q4.x);
    atomicAdd(&sms[k*4+1], s4.y); atomicAdd(&smq[k*4+1], q4.y);
    atomicAdd(&sms[k*4+2], s4.z); atomicAdd(&smq[k*4+2], q4.z);
    atomicAdd(&sms[k*4+3], s4.w); atomicAdd(&smq[k*4+3], q4.w);
    __syncthreads();
    if (t < 64) { atomicAdd(&g_stats[t], sms[t]); atomicAdd(&g_stats[64+t], smq[t]); }
}

// ---------------- bn2 stats from agg (bn1 finalized inline from g_stats) ----------------
__global__ void k_hz2(const float* __restrict__ b_gnn, const float* __restrict__ W_emb,
                      const float* __restrict__ g1, const float* __restrict__ b1v) {
    __shared__ float sA[64], sB[64], sm_s[64], sm_q[64];
    int t = threadIdx.x;
    if (t < 64) {
        float s = g_stats[t], q = g_stats[64+t];
        float m = s * (1.f/NT);
        float v = q * (1.f/NT) - m*m;
        float sc = g1[t] * rsqrtf(v + EPS);
        sA[t] = sc;
        sB[t] = fmaf(b_gnn[t], sc, b1v[t] - m*sc);
        sm_s[t] = 0.f; sm_q[t] = 0.f;
    }
    __syncthreads();
    int gt = blockIdx.x*256 + t;
    int c0 = (gt & 31)*2;
    float A0 = sA[c0], A1 = sA[c0+1];
    float B0 = sB[c0], B1 = sB[c0+1];
    float s0=0,q0=0,s1=0,q1=0;
    const float2* a2 = (const float2*)g_agg;
    const int stride = 1024*256;
    for (int idx = gt; idx < NT*32; idx += stride) {
        int row = idx >> 5;
        int v = row & (NODE-1);
        float2 a = a2[idx];
        float h0 = fmaxf(fmaf(a.x, A0, B0), 0.f);
        float h1 = fmaxf(fmaf(a.y, A1, B1), 0.f);
        float2 we = *(const float2*)&W_emb[v*EMB + c0];
        float z0 = h0 * we.x;
        float z1 = h1 * we.y;
        s0 += z0; q0 += z0*z0; s1 += z1; q1 += z1*z1;
    }
    atomicAdd(&sm_s[c0],   s0); atomicAdd(&sm_q[c0],   q0);
    atomicAdd(&sm_s[c0+1], s1); atomicAdd(&sm_q[c0+1], q1);
    __syncthreads();
    if (t < 64) { atomicAdd(&g_stats[128+t], sm_s[t]); atomicAdd(&g_stats[192+t], sm_q[t]); }
}

// ---------------- zr from agg (bn1+bn2 inline); emit bf16 hi/lo; SYRK + colsum ----------------
__global__ void __launch_bounds__(256, 2)
k_zr(const float* __restrict__ b_gnn, const float* __restrict__ W_emb,
     const float* __restrict__ g1, const float* __restrict__ b1v,
     const float* __restrict__ g2, const float* __restrict__ b2v) {
    __shared__ float zs[128*68];
    __shared__ float cA[64], cB[64], c2s[64], c2h[64];
    __shared__ float red[256];
    int t = threadIdx.x;
    if (t < 64) {
        float s = g_stats[t], q = g_stats[64+t];
        float m = s * (1.f/NT);
        float v = q * (1.f/NT) - m*m;
        float sc = g1[t] * rsqrtf(v + EPS);
        cA[t] = sc;
        cB[t] = fmaf(b_gnn[t], sc, b1v[t] - m*sc);
        s = g_stats[128+t]; q = g_stats[192+t];
        m = s * (1.f/NT);
        v = q * (1.f/NT) - m*m;
        sc = g2[t] * rsqrtf(v + EPS);
        c2s[t] = sc;
        c2h[t] = b2v[t] - m*sc;
    }
    int tx = t & 15, ty = t >> 4;
    int a0 = ty*4, b0 = tx*4;
    float acc[4][4];
    #pragma unroll
    for (int i = 0; i < 4; i++)
        #pragma unroll
        for (int j = 0; j < 4; j++) acc[i][j] = 0.f;
    float csum = 0.f;
    int cc = t & 63, rr0 = t >> 6;
    for (int tile = blockIdx.x; tile < NT/128; tile += gridDim.x) {
        int row0 = tile << 7;
        __syncthreads();
        for (int i = t; i < 128*32; i += 256) {
            int r = i >> 5, k2 = i & 31, c0 = k2*2;
            int v = (row0 + r) & (NODE-1);
            float2 a = ((const float2*)g_agg)[row0*32 + i];
            float2 we = *(const float2*)&W_emb[v*EMB + c0];
            float h0 = fmaxf(fmaf(a.x, cA[c0],   cB[c0]),   0.f);
            float h1 = fmaxf(fmaf(a.y, cA[c0+1], cB[c0+1]), 0.f);
            float z0 = fmaxf(fmaf(h0*we.x, c2s[c0],   c2h[c0]),   0.f);
            float z1 = fmaxf(fmaf(h1*we.y, c2s[c0+1], c2h[c0+1]), 0.f);
            zs[r*68 + c0] = z0; zs[r*68 + c0 + 1] = z1;
            uint32_t lo, hi = packsplit(z0, z1, &lo);
            int j = (row0 + r)*32 + fragperm(k2);
            g_zrh[j] = hi;
            g_zrl[j] = lo;
        }
        __syncthreads();
        for (int r = rr0; r < 128; r += 4) csum += zs[r*68 + cc];
        #pragma unroll 4
        for (int r = 0; r < 128; r++) {
            float4 va = *(const float4*)&zs[r*68 + a0];
            float4 vb = *(const float4*)&zs[r*68 + b0];
            float av[4] = {va.x, va.y, va.z, va.w};
            float bv[4] = {vb.x, vb.y, vb.z, vb.w};
            #pragma unroll
            for (int i = 0; i < 4; i++)
                #pragma unroll
                for (int j = 0; j < 4; j++) acc[i][j] += av[i]*bv[j];
        }
    }
    __syncthreads();
    red[t] = csum;
    __syncthreads();
    if (t < 64) atomicAdd(&g_stats[256 + t], red[t] + red[64+t] + red[128+t] + red[192+t]);
    #pragma unroll
    for (int i = 0; i < 4; i++)
        #pragma unroll
        for (int j = 0; j < 4; j++)
            atomicAdd(&g_stats[320 + (a0+i)*64 + b0 + j], acc[i][j]);
}

// ---------------- analytic BN3: pack {sc,sh,w2} ----------------
__global__ void k_bn3fin(const float* __restrict__ W1, const float* __restrict__ b1,
                         const float* __restrict__ g3, const float* __restrict__ b3,
                         const float* __restrict__ W2) {
    __shared__ float Cov[EMB*EMB];
    __shared__ float zb[EMB];
    int t = threadIdx.x;
    for (int i = t; i < EMB; i += 32) zb[i] = g_stats[256+i] * (1.f/NT);
    __syncthreads();
    for (int i = t; i < EMB*EMB; i += 32)
        Cov[i] = g_stats[320+i] * (1.f/NT) - zb[i >> 6]*zb[i & 63];
    __syncthreads();
    int c = blockIdx.x*32 + t;
    const float* wc = W1 + c*EMB;
    float wr[EMB];
    #pragma unroll
    for (int k = 0; k < EMB; k++) wr[k] = wc[k];
    float m = b1[c];
    #pragma unroll
    for (int k = 0; k < EMB; k++) m += zb[k]*wr[k];
    float var = 0.f;
    for (int a = 0; a < EMB; a++) {
        float ta = 0.f;
        #pragma unroll 8
        for (int b = 0; b < EMB; b++) ta += Cov[a*EMB + b]*wr[b];
        var += ta * wr[a];
    }
    float sc = g3[c] * rsqrtf(var + EPS);
    g_abc[c] = make_float4(sc, b3[c] - m*sc, W2[c], 0.f);
}

// ---------------- final: split-N HMMA GEMM, A direct from gmem, atomic output ----------------
#define F2_BH  0
#define F2_BL  9216
#define F2_ABC 18432
#define SMEM_F2 ((18432 + 1024)*4)   /* 77824 B -> 2 CTAs/SM */

__global__ void __launch_bounds__(256, 2)
k_final_mma(const float* __restrict__ b2, float* __restrict__ out) {
    extern __shared__ uint32_t sm4[];
    uint32_t* Bh = sm4 + F2_BH;
    uint32_t* Bl = sm4 + F2_BL;
    float4*   abc = (float4*)(sm4 + F2_ABC);
    int t = threadIdx.x, lane = t & 31, wid = t >> 5;
    int g = lane >> 2, tid = lane & 3;
    int half = blockIdx.x & 1;
    const uint32_t* wh = g_W1h + half*256*32;
    const uint32_t* wl = g_W1l + half*256*32;
    for (int i = t; i < 256*32; i += 256) {
        int n = i >> 5, k2 = i & 31;
        Bh[n*36 + k2] = wh[i];
        Bl[n*36 + k2] = wl[i];
    }
    for (int i = t; i < 256; i += 256) abc[i] = g_abc[half*256 + i];
    float bb = half ? 0.f : b2[0];
    __syncthreads();

    int tstep = gridDim.x >> 1;
    for (int tile = blockIdx.x >> 1; tile < NT/128; tile += tstep) {
        int row = (tile << 7) + wid*16 + g;
        const uint4* zh0 = (const uint4*)(g_zrh + row*32);
        const uint4* zl0 = (const uint4*)(g_zrl + row*32);
        // row stride = 32 words = 8 uint4, so row+8 => +64 uint4
        uint4 qh0 = zh0[tid*2],      qh1 = zh0[tid*2 + 1];
        uint4 qh2 = zh0[tid*2 + 64], qh3 = zh0[tid*2 + 65];
        uint4 ql0 = zl0[tid*2],      ql1 = zl0[tid*2 + 1];
        uint4 ql2 = zl0[tid*2 + 64], ql3 = zl0[tid*2 + 65];
        uint32_t ah[4][4] = {
            {qh0.x, qh2.x, qh0.y, qh2.y}, {qh0.z, qh2.z, qh0.w, qh2.w},
            {qh1.x, qh3.x, qh1.y, qh3.y}, {qh1.z, qh3.z, qh1.w, qh3.w}};
        uint32_t al[4][4] = {
            {ql0.x, ql2.x, ql0.y, ql2.y}, {ql0.z, ql2.z, ql0.w, ql2.w},
            {ql1.x, ql3.x, ql1.y, ql3.y}, {ql1.z, ql3.z, ql1.w, ql3.w}};
        float part0 = 0.f, part1 = 0.f;
        #pragma unroll 4
        for (int nt = 0; nt < 32; nt++) {
            int nb = (nt*8 + g)*36 + tid*8;
            uint4 bh0 = *(const uint4*)&Bh[nb], bh1 = *(const uint4*)&Bh[nb+4];
            uint4 bl0 = *(const uint4*)&Bl[nb], bl1 = *(const uint4*)&Bl[nb+4];
            float hh[4]={0,0,0,0}, hl[4]={0,0,0,0}, lh[4]={0,0,0,0};
            mma16816(hh, ah[0], bh0.x, bh0.y); mma16816(hh, ah[1], bh0.z, bh0.w);
            mma16816(hh, ah[2], bh1.x, bh1.y); mma16816(hh, ah[3], bh1.z, bh1.w);
            mma16816(hl, ah[0], bl0.x, bl0.y); mma16816(hl, ah[1], bl0.z, bl0.w);
            mma16816(hl, ah[2], bl1.x, bl1.y); mma16816(hl, ah[3], bl1.z, bl1.w);
            mma16816(lh, al[0], bh0.x, bh0.y); mma16816(lh, al[1], bh0.z, bh0.w);
            mma16816(lh, al[2], bh1.x, bh1.y); mma16816(lh, al[3], bh1.z, bh1.w);
            float4 p0 = abc[nt*8 + tid*2];
            float4 p1 = abc[nt*8 + tid*2 + 1];
            float y;
            y = fmaxf(fmaf(hh[0]+hl[0]+lh[0], p0.x, p0.y), 0.f); part0 = fmaf(y, p0.z, part0);
            y = fmaxf(fmaf(hh[1]+hl[1]+lh[1], p1.x, p1.y), 0.f); part0 = fmaf(y, p1.z, part0);
            y = fmaxf(fmaf(hh[2]+hl[2]+lh[2], p0.x, p0.y), 0.f); part1 = fmaf(y, p0.z, part1);
            y = fmaxf(fmaf(hh[3]+hl[3]+lh[3], p1.x, p1.y), 0.f); part1 = fmaf(y, p1.z, part1);
        }
        part0 += __shfl_xor_sync(0xffffffffu, part0, 1);
        part0 += __shfl_xor_sync(0xffffffffu, part0, 2);
        part1 += __shfl_xor_sync(0xffffffffu, part1, 1);
        part1 += __shfl_xor_sync(0xffffffffu, part1, 2);
        if (tid == 0) {
            atomicAdd(&out[row],     part0 + bb);
            atomicAdd(&out[row + 8], part1 + bb);
        }
    }
}

// ---------------- launch ----------------
extern "C" void kernel_launch(void* const* d_in, const int* in_sizes, int n_in,
                              void* d_out, int out_size) {
    const float* data     = (const float*)d_in[0];
    const float* W_emb    = (const float*)d_in[2];
    const float* W_lin    = (const float*)d_in[3];
    const float* att_i    = (const float*)d_in[4];
    const float* att_j    = (const float*)d_in[5];
    const float* att_em_i = (const float*)d_in[6];
    const float* att_em_j = (const float*)d_in[7];
    const float* b_gnn    = (const float*)d_in[8];
    const float* gbn1     = (const float*)d_in[9];
    const float* bbn1     = (const float*)d_in[10];
    const float* gbn2     = (const float*)d_in[11];
    const float* bbn2     = (const float*)d_in[12];
    const float* W1       = (const float*)d_in[13];
    const float* b1       = (const float*)d_in[14];
    const float* gbn3     = (const float*)d_in[15];
    const float* bbn3     = (const float*)d_in[16];
    const float* W2       = (const float*)d_in[17];
    const float* b2       = (const float*)d_in[18];
    float* out = (float*)d_out;

    cudaFuncSetAttribute(k_xl_mma,    cudaFuncAttributeMaxDynamicSharedMemorySize, SMEM_XL);
    cudaFuncSetAttribute(k_agg,       cudaFuncAttributeMaxDynamicSharedMemorySize, SMEM_AGG);
    cudaFuncSetAttribute(k_final_mma, cudaFuncAttributeMaxDynamicSharedMemorySize, SMEM_F2);
    int nsm = 0;
    cudaDeviceGetAttribute(&nsm, cudaDevAttrMultiProcessorCount, 0);
    if (nsm <= 0) nsm = 148;

    k_prep<<<98, 512>>>(W_emb, att_em_i, att_em_j, W1, out);
    k_topk<<<64, 256>>>(W_emb);
    k_xl_mma<<<nsm*2, 256, SMEM_XL>>>(data, W_lin, att_i, att_j);
    k_agg<<<BATCH, 1024, SMEM_AGG>>>(b_gnn);
    k_hz2<<<1024, 256>>>(b_gnn, W_emb, gbn1, bbn1);
    k_zr<<<nsm*2, 256>>>(b_gnn, W_emb, gbn1, bbn1, gbn2, bbn2);
    k_bn3fin<<<16, 32>>>(W1, b1, gbn3, bbn3, W2);
    k_final_mma<<<nsm*2, 256, SMEM_F2>>>(b2, out);
}